// round 1
// baseline (speedup 1.0000x reference)
#include <cuda_runtime.h>

#define NN 100000
#define EE 1600000
#define FF 128

typedef unsigned long long ull;

// ---------------- device scratch (allocation-free) ----------------
__device__ int   g_deg[NN];
__device__ int   g_rowptr[NN + 1];
__device__ int   g_cnt[NN];
__device__ int   g_dsts[EE];
__device__ float g_norm[NN];
__device__ __align__(16) float g_bufA[(size_t)NN * FF];
__device__ __align__(16) float g_bufB[(size_t)NN * FF];
__device__ __align__(16) float4 g_scal[NN];
__device__ __align__(16) float g_wr0rs[FF];

// ---------------- f32x2 helpers ----------------
__device__ __forceinline__ ull pack2(float x) {
    ull r;
    asm("mov.b64 %0, {%1, %1};" : "=l"(r) : "f"(x));
    return r;
}
__device__ __forceinline__ void fma2(ull& d, ull a, ull b) {
    asm("fma.rn.f32x2 %0, %1, %2, %0;" : "+l"(d) : "l"(a), "l"(b));
}

// ---------------- graph preprocessing ----------------
__global__ void k_zero() {
    int i = blockIdx.x * blockDim.x + threadIdx.x;
    if (i < NN) g_deg[i] = 0;
}

__global__ void k_hist(const int* __restrict__ src) {
    int e = blockIdx.x * blockDim.x + threadIdx.x;
    if (e < EE) atomicAdd(&g_deg[src[e]], 1);
}

// single-block scan over N=100000 degrees; also writes norm and fill counters
__global__ void k_scan() {
    __shared__ int sums[1024];
    int t = threadIdx.x;
    const int chunk = (NN + 1023) / 1024;  // 98
    int start = t * chunk;
    int end = min(start + chunk, NN);
    int s = 0;
    for (int i = start; i < end; i++) s += g_deg[i];
    sums[t] = s;
    __syncthreads();
    for (int off = 1; off < 1024; off <<= 1) {
        int v = (t >= off) ? sums[t - off] : 0;
        __syncthreads();
        sums[t] += v;
        __syncthreads();
    }
    int run = sums[t] - s;  // exclusive prefix for this chunk
    for (int i = start; i < end; i++) {
        int d = g_deg[i];
        g_rowptr[i] = run;
        g_cnt[i] = run;
        g_norm[i] = rsqrtf((float)d);
        run += d;
    }
    if (t == 1023) g_rowptr[NN] = sums[1023];
}

__global__ void k_fill(const int* __restrict__ src, const int* __restrict__ dst) {
    int e = blockIdx.x * blockDim.x + threadIdx.x;
    if (e < EE) {
        int pos = atomicAdd(&g_cnt[src[e]], 1);
        g_dsts[pos] = dst[e];
    }
}

// ---------------- GEMM: Y = (Xin * norm_row) @ W  [N,128]x[128,128] ----------------
// block: 256 threads, 64 rows x 128 cols per block, f32x2 packed FMA
__global__ void __launch_bounds__(256) k_gemm(const float* __restrict__ Xin,
                                              const float* __restrict__ W,
                                              float* __restrict__ Y) {
    extern __shared__ float smem[];
    float* Ws = smem;              // 128*128
    float* Xs = smem + 128 * 128;  // [k][row] transposed, padded stride 68

    int tid = threadIdx.x;
    int row0 = blockIdx.x * 64;

    for (int i = tid; i < 128 * 128; i += 256) Ws[i] = W[i];
    for (int i = tid; i < 64 * 128; i += 256) {
        int r = i >> 7, k = i & 127;
        int row = row0 + r;
        float v = 0.f;
        if (row < NN) v = Xin[(size_t)row * 128 + k] * g_norm[row];
        Xs[k * 68 + r] = v;
    }
    __syncthreads();

    int rg = tid >> 4;  // 0..15 -> rows rg*4 .. rg*4+3
    int cg = tid & 15;  // cols cg*8 .. cg*8+7 (4 col-pairs)

    ull acc[4][4];
#pragma unroll
    for (int r = 0; r < 4; r++)
#pragma unroll
        for (int j = 0; j < 4; j++) acc[r][j] = 0ull;

    for (int k = 0; k < 128; k++) {
        float4 xv = *(const float4*)&Xs[k * 68 + rg * 4];
        const ulonglong2* wp = (const ulonglong2*)&Ws[k * 128 + cg * 8];
        ulonglong2 wa = wp[0];
        ulonglong2 wb = wp[1];
        ull xp0 = pack2(xv.x), xp1 = pack2(xv.y), xp2 = pack2(xv.z), xp3 = pack2(xv.w);
        fma2(acc[0][0], xp0, wa.x); fma2(acc[0][1], xp0, wa.y);
        fma2(acc[0][2], xp0, wb.x); fma2(acc[0][3], xp0, wb.y);
        fma2(acc[1][0], xp1, wa.x); fma2(acc[1][1], xp1, wa.y);
        fma2(acc[1][2], xp1, wb.x); fma2(acc[1][3], xp1, wb.y);
        fma2(acc[2][0], xp2, wa.x); fma2(acc[2][1], xp2, wa.y);
        fma2(acc[2][2], xp2, wb.x); fma2(acc[2][3], xp2, wb.y);
        fma2(acc[3][0], xp3, wa.x); fma2(acc[3][1], xp3, wa.y);
        fma2(acc[3][2], xp3, wb.x); fma2(acc[3][3], xp3, wb.y);
    }

#pragma unroll
    for (int r = 0; r < 4; r++) {
        int row = row0 + rg * 4 + r;
        if (row < NN) {
            ull* yp = (ull*)&Y[(size_t)row * 128 + cg * 8];
            yp[0] = acc[r][0]; yp[1] = acc[r][1];
            yp[2] = acc[r][2]; yp[3] = acc[r][3];
        }
    }
}

// ---------------- aggregation: Y[i] = norm[i] * sum_{e in row i} Xin[dst[e]] ----------------
// warp per node, lane covers 4 feature floats
__global__ void k_agg(const float* __restrict__ Xin, float* __restrict__ Y) {
    int gt = blockIdx.x * blockDim.x + threadIdx.x;
    int node = gt >> 5;
    int lane = gt & 31;
    if (node >= NN) return;

    int e = g_rowptr[node];
    int end = g_rowptr[node + 1];

    float4 a0 = make_float4(0.f, 0.f, 0.f, 0.f);
    float4 a1 = make_float4(0.f, 0.f, 0.f, 0.f);

    for (; e + 2 <= end; e += 2) {
        int da = g_dsts[e];
        int db = g_dsts[e + 1];
        float4 va = *(const float4*)(Xin + (size_t)da * 128 + lane * 4);
        float4 vb = *(const float4*)(Xin + (size_t)db * 128 + lane * 4);
        a0.x += va.x; a0.y += va.y; a0.z += va.z; a0.w += va.w;
        a1.x += vb.x; a1.y += vb.y; a1.z += vb.z; a1.w += vb.w;
    }
    if (e < end) {
        int da = g_dsts[e];
        float4 va = *(const float4*)(Xin + (size_t)da * 128 + lane * 4);
        a0.x += va.x; a0.y += va.y; a0.z += va.z; a0.w += va.w;
    }
    float nm = g_norm[node];
    float4 r;
    r.x = (a0.x + a1.x) * nm;
    r.y = (a0.y + a1.y) * nm;
    r.z = (a0.z + a1.z) * nm;
    r.w = (a0.w + a1.w) * nm;
    *(float4*)(Y + (size_t)node * 128 + lane * 4) = r;
}

// ---------------- head weights: row-sum of w_rate0 ----------------
__global__ void k_wr0rs(const float* __restrict__ w0) {
    int k = threadIdx.x;
    if (k < FF) {
        float s = 0.f;
        for (int f = 0; f < FF; f++) s += w0[k * FF + f];
        g_wr0rs[k] = s;
    }
}

// ---------------- per-node scalars: r0sum, r1, alpha ----------------
__global__ void k_scal(const float* __restrict__ h2, const float* __restrict__ w1,
                       const float* __restrict__ wa) {
    int gt = blockIdx.x * blockDim.x + threadIdx.x;
    int node = gt >> 5;
    int lane = gt & 31;
    if (node >= NN) return;

    float4 h = *(const float4*)(h2 + (size_t)node * 128 + lane * 4);
    float4 a = *(const float4*)(g_wr0rs + lane * 4);
    float4 b = *(const float4*)(w1 + lane * 4);
    float4 c = *(const float4*)(wa + lane * 4);

    float s0 = h.x * a.x + h.y * a.y + h.z * a.z + h.w * a.w;
    float s1 = h.x * b.x + h.y * b.y + h.z * b.z + h.w * b.w;
    float s2 = h.x * c.x + h.y * c.y + h.z * c.z + h.w * c.w;

#pragma unroll
    for (int off = 16; off; off >>= 1) {
        s0 += __shfl_xor_sync(0xffffffffu, s0, off);
        s1 += __shfl_xor_sync(0xffffffffu, s1, off);
        s2 += __shfl_xor_sync(0xffffffffu, s2, off);
    }
    if (lane == 0) {
        float4 o;
        o.x = s0; o.y = s1; o.z = s2; o.w = 0.f;
        g_scal[node] = o;
    }
}

// ---------------- per-edge outputs [6, E] ----------------
__device__ __forceinline__ float sigm(float x) { return 1.f / (1.f + expf(-x)); }

__global__ void k_edge(const int* __restrict__ src, const int* __restrict__ dst,
                       const int* __restrict__ sfk, const int* __restrict__ dfk,
                       float* __restrict__ out) {
    int e = blockIdx.x * blockDim.x + threadIdx.x;
    if (e >= EE) return;
    int s = src[e];
    int d = dst[e];
    int a = min(sfk[e], NN - 1);  // JAX gather clamps OOB indices
    int b = min(dfk[e], NN - 1);

    float4 S = g_scal[s];
    float4 D = g_scal[d];
    float4 A = g_scal[a];
    float4 B = g_scal[b];

    out[e]            = expf(S.x + D.x);                 // rate0_real
    out[EE + e]       = expf(S.y + D.y);                 // rate1_real
    out[2 * EE + e]   = sigm(S.z * D.z);                 // alpha_real (/sqrt(1))
    out[3 * EE + e]   = expf(A.x + 128.f * B.y);         // rate0_fake
    out[4 * EE + e]   = expf(A.y + B.y);                 // rate1_fake
    out[5 * EE + e]   = sigm(S.z * B.z);                 // alpha_fake (/1)
}

// ---------------- launch ----------------
extern "C" void kernel_launch(void* const* d_in, const int* in_sizes, int n_in,
                              void* d_out, int out_size) {
    const float* h   = (const float*)d_in[0];
    const float* w0  = (const float*)d_in[1];
    const float* w1  = (const float*)d_in[2];
    const float* wr0 = (const float*)d_in[3];
    const float* wr1 = (const float*)d_in[4];
    const float* wal = (const float*)d_in[5];
    const int* esrc  = (const int*)d_in[6];
    const int* edst  = (const int*)d_in[7];
    const int* sfk   = (const int*)d_in[8];
    const int* dfk   = (const int*)d_in[9];
    float* out = (float*)d_out;

    const int GEMM_SMEM = (128 * 128 + 128 * 68) * 4;  // 100352 bytes
    cudaFuncSetAttribute(k_gemm, cudaFuncAttributeMaxDynamicSharedMemorySize, GEMM_SMEM);

    float* bufA = nullptr;
    float* bufB = nullptr;
    cudaGetSymbolAddress((void**)&bufA, g_bufA);
    cudaGetSymbolAddress((void**)&bufB, g_bufB);

    // graph preprocessing
    k_zero<<<(NN + 511) / 512, 512>>>();
    k_hist<<<(EE + 511) / 512, 512>>>(esrc);
    k_scan<<<1, 1024>>>();
    k_fill<<<(EE + 511) / 512, 512>>>(esrc, edst);

    int gemm_blocks = (NN + 63) / 64;
    int warp_blocks = (NN * 32 + 255) / 256;

    // GCN layer 1: bufA = (h*norm)@W0 ; bufB = norm * segsum(bufA)
    k_gemm<<<gemm_blocks, 256, GEMM_SMEM>>>(h, w0, bufA);
    k_agg<<<warp_blocks, 256>>>(bufA, bufB);

    // GCN layer 2: bufA = (bufB*norm)@W1 ; bufB = norm * segsum(bufA)  (= h2)
    k_gemm<<<gemm_blocks, 256, GEMM_SMEM>>>(bufB, w1, bufA);
    k_agg<<<warp_blocks, 256>>>(bufA, bufB);

    // heads
    k_wr0rs<<<1, 128>>>(wr0);
    k_scal<<<warp_blocks, 256>>>(bufB, wr1, wal);

    // per-edge outputs
    k_edge<<<(EE + 255) / 256, 256>>>(esrc, edst, sfk, dfk, out);
}

// round 2
// speedup vs baseline: 4.8598x; 4.8598x over previous
#include <cuda_runtime.h>

#define NN 100000
#define EE 1600000
#define NB 391  // ceil(NN/256)

// ---------------- device scratch (allocation-free) ----------------
__device__ int   g_deg[NN];
__device__ int   g_rowptr[NN + 1];
__device__ int   g_cnt[NN];
__device__ int   g_dsts[EE];
__device__ float g_norm[NN];
__device__ int   g_bsum[NB];
__device__ int   g_boff[NB];
__device__ __align__(16) float4 g_M[128];     // folded weights: 128 x (3 used + pad)
__device__ __align__(16) float4 g_t[NN];      // layer-1 pre-normed projection
__device__ __align__(16) float4 g_x[NN];      // after agg1 + norm^2
__device__ __align__(16) float4 g_scal[NN];   // final per-node scalars

// ---------------- histogram (degree) ----------------
__global__ void k_hist(const int4* __restrict__ src4) {
    int i = blockIdx.x * blockDim.x + threadIdx.x;
    if (i < EE / 4) {
        int4 v = src4[i];
        atomicAdd(&g_deg[v.x], 1);
        atomicAdd(&g_deg[v.y], 1);
        atomicAdd(&g_deg[v.z], 1);
        atomicAdd(&g_deg[v.w], 1);
    }
}

// ---------------- two-level exclusive scan over degrees ----------------
__global__ void k_part() {
    __shared__ int sh[256];
    int idx = blockIdx.x * 256 + threadIdx.x;
    int v = (idx < NN) ? g_deg[idx] : 0;
    sh[threadIdx.x] = v;
    __syncthreads();
#pragma unroll
    for (int o = 128; o; o >>= 1) {
        if (threadIdx.x < o) sh[threadIdx.x] += sh[threadIdx.x + o];
        __syncthreads();
    }
    if (threadIdx.x == 0) g_bsum[blockIdx.x] = sh[0];
}

__global__ void k_scanb() {
    __shared__ int sh[512];
    int t = threadIdx.x;
    int v = (t < NB) ? g_bsum[t] : 0;
    sh[t] = v;
    __syncthreads();
    for (int o = 1; o < 512; o <<= 1) {
        int a = (t >= o) ? sh[t - o] : 0;
        __syncthreads();
        sh[t] += a;
        __syncthreads();
    }
    if (t < NB) g_boff[t] = sh[t] - v;  // exclusive
}

__global__ void k_wptr() {
    __shared__ int sh[256];
    int t = threadIdx.x;
    int idx = blockIdx.x * 256 + t;
    int d = (idx < NN) ? g_deg[idx] : 0;
    sh[t] = d;
    __syncthreads();
    for (int o = 1; o < 256; o <<= 1) {
        int a = (t >= o) ? sh[t - o] : 0;
        __syncthreads();
        sh[t] += a;
        __syncthreads();
    }
    int pos = g_boff[blockIdx.x] + sh[t] - d;  // exclusive prefix
    if (idx < NN) {
        g_rowptr[idx] = pos;
        g_cnt[idx] = pos;
        g_norm[idx] = rsqrtf((float)d);
    }
    if (idx == 0) g_rowptr[NN] = EE;
}

// ---------------- CSR fill ----------------
__global__ void k_fill(const int* __restrict__ src, const int* __restrict__ dst) {
    int e = blockIdx.x * blockDim.x + threadIdx.x;
    if (e < EE) {
        int pos = atomicAdd(&g_cnt[src[e]], 1);
        g_dsts[pos] = dst[e];
    }
}

// ---------------- fold weights: M = W_gcn0 @ W_gcn1 @ [rowsum(wr0), wr1, wal] ----------------
__global__ void k_weights(const float* __restrict__ w0g, const float* __restrict__ w1g,
                          const float* __restrict__ wr0, const float* __restrict__ wr1,
                          const float* __restrict__ wal) {
    __shared__ float V[128][4];
    __shared__ float U[128][4];
    int k = threadIdx.x;  // 128 threads
    float s = 0.f;
    for (int f = 0; f < 128; f++) s += wr0[k * 128 + f];
    V[k][0] = s;
    V[k][1] = wr1[k];
    V[k][2] = wal[k];
    __syncthreads();
    float s0 = 0.f, s1 = 0.f, s2 = 0.f;
    for (int f = 0; f < 128; f++) {
        float w = w1g[k * 128 + f];
        s0 += w * V[f][0]; s1 += w * V[f][1]; s2 += w * V[f][2];
    }
    U[k][0] = s0; U[k][1] = s1; U[k][2] = s2;
    __syncthreads();
    s0 = s1 = s2 = 0.f;
    for (int f = 0; f < 128; f++) {
        float w = w0g[k * 128 + f];
        s0 += w * U[f][0]; s1 += w * U[f][1]; s2 += w * U[f][2];
    }
    g_M[k] = make_float4(s0, s1, s2, 0.f);
}

// ---------------- t = norm * (h @ M)  (warp per node) ----------------
__global__ void __launch_bounds__(256) k_t(const float4* __restrict__ h4) {
    int gt = blockIdx.x * blockDim.x + threadIdx.x;
    int node = gt >> 5;
    int lane = gt & 31;
    if (node >= NN) return;

    float4 hv = __ldg(&h4[(size_t)node * 32 + lane]);
    float4 m0 = g_M[lane * 4 + 0];
    float4 m1 = g_M[lane * 4 + 1];
    float4 m2 = g_M[lane * 4 + 2];
    float4 m3 = g_M[lane * 4 + 3];

    float s0 = hv.x * m0.x + hv.y * m1.x + hv.z * m2.x + hv.w * m3.x;
    float s1 = hv.x * m0.y + hv.y * m1.y + hv.z * m2.y + hv.w * m3.y;
    float s2 = hv.x * m0.z + hv.y * m1.z + hv.z * m2.z + hv.w * m3.z;

#pragma unroll
    for (int o = 16; o; o >>= 1) {
        s0 += __shfl_xor_sync(0xffffffffu, s0, o);
        s1 += __shfl_xor_sync(0xffffffffu, s1, o);
        s2 += __shfl_xor_sync(0xffffffffu, s2, o);
    }
    if (lane == 0) {
        float nm = g_norm[node];
        g_t[node] = make_float4(s0 * nm, s1 * nm, s2 * nm, 0.f);
    }
}

// ---------------- aggregation on 3-wide vectors (thread per node) ----------------
// mode 0: scale = norm^2 (post-norm L1 * pre-norm L2); mode 1: scale = norm (final)
__global__ void k_agg3(const float4* __restrict__ in, float4* __restrict__ out, int mode) {
    int i = blockIdx.x * blockDim.x + threadIdx.x;
    if (i >= NN) return;
    int e = g_rowptr[i];
    int end = g_rowptr[i + 1];

    float x0 = 0.f, y0 = 0.f, z0 = 0.f;
    float x1 = 0.f, y1 = 0.f, z1 = 0.f;

    for (; e + 2 <= end; e += 2) {
        int a = g_dsts[e];
        int b = g_dsts[e + 1];
        float4 va = __ldg(&in[a]);
        float4 vb = __ldg(&in[b]);
        x0 += va.x; y0 += va.y; z0 += va.z;
        x1 += vb.x; y1 += vb.y; z1 += vb.z;
    }
    if (e < end) {
        float4 v = __ldg(&in[g_dsts[e]]);
        x0 += v.x; y0 += v.y; z0 += v.z;
    }
    float nm = g_norm[i];
    float sc = mode ? nm : nm * nm;
    out[i] = make_float4((x0 + x1) * sc, (y0 + y1) * sc, (z0 + z1) * sc, 0.f);
}

// ---------------- per-edge outputs [6, E] ----------------
__device__ __forceinline__ float sigm(float x) { return 1.f / (1.f + expf(-x)); }

__global__ void k_edge(const int* __restrict__ src, const int* __restrict__ dst,
                       const int* __restrict__ sfk, const int* __restrict__ dfk,
                       float* __restrict__ out) {
    int e = blockIdx.x * blockDim.x + threadIdx.x;
    if (e >= EE) return;
    int s = src[e];
    int d = dst[e];
    int a = min(sfk[e], NN - 1);  // JAX gather clamps OOB indices
    int b = min(dfk[e], NN - 1);

    float4 S = g_scal[s];
    float4 D = g_scal[d];
    float4 A = g_scal[a];
    float4 B = g_scal[b];

    out[e]          = expf(S.x + D.x);          // rate0_real
    out[EE + e]     = expf(S.y + D.y);          // rate1_real
    out[2 * EE + e] = sigm(S.z * D.z);          // alpha_real
    out[3 * EE + e] = expf(A.x + 128.f * B.y);  // rate0_fake
    out[4 * EE + e] = expf(A.y + B.y);          // rate1_fake
    out[5 * EE + e] = sigm(S.z * B.z);          // alpha_fake
}

// ---------------- launch ----------------
extern "C" void kernel_launch(void* const* d_in, const int* in_sizes, int n_in,
                              void* d_out, int out_size) {
    const float* h   = (const float*)d_in[0];
    const float* w0g = (const float*)d_in[1];
    const float* w1g = (const float*)d_in[2];
    const float* wr0 = (const float*)d_in[3];
    const float* wr1 = (const float*)d_in[4];
    const float* wal = (const float*)d_in[5];
    const int* esrc  = (const int*)d_in[6];
    const int* edst  = (const int*)d_in[7];
    const int* sfk   = (const int*)d_in[8];
    const int* dfk   = (const int*)d_in[9];
    float* out = (float*)d_out;

    void* degp = nullptr;
    cudaGetSymbolAddress(&degp, g_deg);
    float4* tp = nullptr; float4* xp = nullptr; float4* scp = nullptr;
    cudaGetSymbolAddress((void**)&tp, g_t);
    cudaGetSymbolAddress((void**)&xp, g_x);
    cudaGetSymbolAddress((void**)&scp, g_scal);

    // preprocessing: degree histogram -> scan -> CSR fill
    cudaMemsetAsync(degp, 0, NN * sizeof(int));
    k_hist<<<(EE / 4 + 255) / 256, 256>>>((const int4*)esrc);
    k_part<<<NB, 256>>>();
    k_scanb<<<1, 512>>>();
    k_wptr<<<NB, 256>>>();
    k_fill<<<(EE + 511) / 512, 512>>>(esrc, edst);

    // fold all weights into 128x3 (independent of graph preproc)
    k_weights<<<1, 128>>>(w0g, w1g, wr0, wr1, wal);

    // t = norm * (h @ M)
    k_t<<<(NN * 32 + 255) / 256, 256>>>((const float4*)h);

    // two 3-wide aggregation passes: x = norm^2 * (A t); scal = norm * (A x)
    k_agg3<<<(NN + 255) / 256, 256>>>(tp, xp, 0);
    k_agg3<<<(NN + 255) / 256, 256>>>(xp, scp, 1);

    // per-edge outputs
    k_edge<<<(EE + 255) / 256, 256>>>(esrc, edst, sfk, dfk, out);
}

// round 3
// speedup vs baseline: 5.1522x; 1.0602x over previous
#include <cuda_runtime.h>

#define NN 100000
#define EE 1600000

// ---------------- device scratch (allocation-free) ----------------
__device__ int   g_deg[NN];
__device__ float g_norm[NN];
__device__ __align__(16) float4 g_M[128];   // folded weights: 128 x (3 used + pad)
__device__ __align__(16) float4 g_t[NN];    // norm * (h @ M)
__device__ __align__(16) float4 g_x[NN];    // agg-1 accumulator
__device__ __align__(16) float4 g_s[NN];    // agg-2 accumulator
__device__ __align__(16) float4 g_p[NN];    // precomputed per-node factors

// ---------------- vector RED helper ----------------
__device__ __forceinline__ void red_add_v4(float4* addr, float x, float y, float z) {
    asm volatile("red.global.add.v4.f32 [%0], {%1, %2, %3, %4};"
                 :: "l"(addr), "f"(x), "f"(y), "f"(z), "f"(0.f) : "memory");
}

__device__ __forceinline__ float sigm_tanh(float v) {
    float t;
    asm("tanh.approx.f32 %0, %1;" : "=f"(t) : "f"(0.5f * v));
    return fmaf(0.5f, t, 0.5f);
}

// ---------------- degree histogram ----------------
__global__ void k_hist(const int4* __restrict__ src4) {
    int i = blockIdx.x * blockDim.x + threadIdx.x;
    if (i < EE / 4) {
        int4 v = src4[i];
        atomicAdd(&g_deg[v.x], 1);
        atomicAdd(&g_deg[v.y], 1);
        atomicAdd(&g_deg[v.z], 1);
        atomicAdd(&g_deg[v.w], 1);
    }
}

__global__ void k_norm() {
    int i = blockIdx.x * blockDim.x + threadIdx.x;
    if (i < NN) g_norm[i] = rsqrtf((float)g_deg[i]);
}

// ---------------- fold weights: M = W0 @ W1 @ [rowsum(wr0), wr1, wal] ----------------
__global__ void k_weights(const float* __restrict__ w0g, const float* __restrict__ w1g,
                          const float* __restrict__ wr0, const float* __restrict__ wr1,
                          const float* __restrict__ wal) {
    __shared__ float V[128][4];
    __shared__ float U[128][4];
    int k = threadIdx.x;  // 128 threads
    float s = 0.f;
    for (int f = 0; f < 128; f++) s += wr0[k * 128 + f];
    V[k][0] = s;
    V[k][1] = wr1[k];
    V[k][2] = wal[k];
    __syncthreads();
    float s0 = 0.f, s1 = 0.f, s2 = 0.f;
    for (int f = 0; f < 128; f++) {
        float w = w1g[k * 128 + f];
        s0 += w * V[f][0]; s1 += w * V[f][1]; s2 += w * V[f][2];
    }
    U[k][0] = s0; U[k][1] = s1; U[k][2] = s2;
    __syncthreads();
    s0 = s1 = s2 = 0.f;
    for (int f = 0; f < 128; f++) {
        float w = w0g[k * 128 + f];
        s0 += w * U[f][0]; s1 += w * U[f][1]; s2 += w * U[f][2];
    }
    g_M[k] = make_float4(s0, s1, s2, 0.f);
}

// ---------------- t = norm * (h @ M)  (warp per node) ----------------
__global__ void __launch_bounds__(256) k_t(const float4* __restrict__ h4) {
    int gt = blockIdx.x * blockDim.x + threadIdx.x;
    int node = gt >> 5;
    int lane = gt & 31;
    if (node >= NN) return;

    float4 hv = __ldg(&h4[(size_t)node * 32 + lane]);
    float4 m0 = g_M[lane * 4 + 0];
    float4 m1 = g_M[lane * 4 + 1];
    float4 m2 = g_M[lane * 4 + 2];
    float4 m3 = g_M[lane * 4 + 3];

    float s0 = hv.x * m0.x + hv.y * m1.x + hv.z * m2.x + hv.w * m3.x;
    float s1 = hv.x * m0.y + hv.y * m1.y + hv.z * m2.y + hv.w * m3.y;
    float s2 = hv.x * m0.z + hv.y * m1.z + hv.z * m2.z + hv.w * m3.z;

#pragma unroll
    for (int o = 16; o; o >>= 1) {
        s0 += __shfl_xor_sync(0xffffffffu, s0, o);
        s1 += __shfl_xor_sync(0xffffffffu, s1, o);
        s2 += __shfl_xor_sync(0xffffffffu, s2, o);
    }
    if (lane == 0) {
        float nm = g_norm[node];
        g_t[node] = make_float4(s0 * nm, s1 * nm, s2 * nm, 0.f);
    }
}

// ---------------- pass 1: x[src] += t[dst]  (scatter RED) ----------------
__global__ void k_agg1(const int* __restrict__ src, const int* __restrict__ dst) {
    int e = blockIdx.x * blockDim.x + threadIdx.x;
    if (e >= EE) return;
    float4 v = __ldg(&g_t[dst[e]]);
    red_add_v4(&g_x[src[e]], v.x, v.y, v.z);
}

// ---------------- pass 2: s[src] += x[dst] * norm[dst]^2 ----------------
__global__ void k_agg2(const int* __restrict__ src, const int* __restrict__ dst) {
    int e = blockIdx.x * blockDim.x + threadIdx.x;
    if (e >= EE) return;
    int d = dst[e];
    float4 v = __ldg(&g_x[d]);
    float nm = __ldg(&g_norm[d]);
    float n2 = nm * nm;
    red_add_v4(&g_s[src[e]], v.x * n2, v.y * n2, v.z * n2);
}

// ---------------- per-node finish: final norm + exp precompute ----------------
__global__ void k_finish() {
    int i = blockIdx.x * blockDim.x + threadIdx.x;
    if (i >= NN) return;
    float4 a = g_s[i];
    float nm = g_norm[i];
    float fx = a.x * nm, fy = a.y * nm, fz = a.z * nm;
    float4 p;
    p.x = expf(fx);          // e^{r0sum}
    p.y = expf(fy);          // e^{r1}
    p.z = fz;                // alpha scalar (raw)
    p.w = expf(128.f * fy);  // e^{128*r1}
    g_p[i] = p;
}

// ---------------- per-edge outputs [6, E] ----------------
__global__ void k_edge(const int* __restrict__ src, const int* __restrict__ dst,
                       const int* __restrict__ sfk, const int* __restrict__ dfk,
                       float* __restrict__ out) {
    int e = blockIdx.x * blockDim.x + threadIdx.x;
    if (e >= EE) return;
    int s = src[e];
    int d = dst[e];
    int a = min(sfk[e], NN - 1);  // JAX gather clamps OOB indices
    int b = min(dfk[e], NN - 1);

    float4 S = __ldg(&g_p[s]);
    float4 D = __ldg(&g_p[d]);
    float4 A = __ldg(&g_p[a]);
    float4 B = __ldg(&g_p[b]);

    out[e]          = S.x * D.x;           // exp(S.x + D.x)
    out[EE + e]     = S.y * D.y;           // exp(S.y + D.y)
    out[2 * EE + e] = sigm_tanh(S.z * D.z);
    out[3 * EE + e] = A.x * B.w;           // exp(A.x + 128*B.y)
    out[4 * EE + e] = A.y * B.y;           // exp(A.y + B.y)
    out[5 * EE + e] = sigm_tanh(S.z * B.z);
}

// ---------------- launch ----------------
extern "C" void kernel_launch(void* const* d_in, const int* in_sizes, int n_in,
                              void* d_out, int out_size) {
    const float* h   = (const float*)d_in[0];
    const float* w0g = (const float*)d_in[1];
    const float* w1g = (const float*)d_in[2];
    const float* wr0 = (const float*)d_in[3];
    const float* wr1 = (const float*)d_in[4];
    const float* wal = (const float*)d_in[5];
    const int* esrc  = (const int*)d_in[6];
    const int* edst  = (const int*)d_in[7];
    const int* sfk   = (const int*)d_in[8];
    const int* dfk   = (const int*)d_in[9];
    float* out = (float*)d_out;

    void *degp = nullptr, *xp = nullptr, *sp = nullptr;
    cudaGetSymbolAddress(&degp, g_deg);
    cudaGetSymbolAddress(&xp, g_x);
    cudaGetSymbolAddress(&sp, g_s);

    // zero accumulators
    cudaMemsetAsync(degp, 0, NN * sizeof(int));
    cudaMemsetAsync(xp, 0, NN * sizeof(float4));
    cudaMemsetAsync(sp, 0, NN * sizeof(float4));

    // degree -> norm
    k_hist<<<(EE / 4 + 255) / 256, 256>>>((const int4*)esrc);
    k_norm<<<(NN + 255) / 256, 256>>>();

    // fold weights (independent)
    k_weights<<<1, 128>>>(w0g, w1g, wr0, wr1, wal);

    // projection
    k_t<<<(NN * 32 + 255) / 256, 256>>>((const float4*)h);

    // two scatter-RED aggregation passes
    k_agg1<<<(EE + 255) / 256, 256>>>(esrc, edst);
    k_agg2<<<(EE + 255) / 256, 256>>>(esrc, edst);

    // per-node exp precompute
    k_finish<<<(NN + 255) / 256, 256>>>();

    // per-edge outputs
    k_edge<<<(EE + 255) / 256, 256>>>(esrc, edst, sfk, dfk, out);
}

// round 4
// speedup vs baseline: 6.0165x; 1.1678x over previous
#include <cuda_runtime.h>

#define NN 100000
#define EE 1600000

// ---------------- device scratch (allocation-free) ----------------
__device__ int   g_deg[NN];
__device__ float g_norm[NN];
__device__ __align__(16) float4 g_M[128];   // folded weights: 128 x (3 used + pad)
__device__ __align__(16) float4 g_t[NN];    // h @ M (raw, then normed in-place)
__device__ __align__(16) float4 g_x[NN];    // agg-1 accumulator
__device__ __align__(16) float4 g_s[NN];    // agg-2 accumulator
__device__ __align__(16) float4 g_p[NN];    // precomputed per-node factors

// ---------------- helpers ----------------
__device__ __forceinline__ void red_add_v4(float4* addr, float x, float y, float z) {
    asm volatile("red.global.add.v4.f32 [%0], {%1, %2, %3, %4};"
                 :: "l"(addr), "f"(x), "f"(y), "f"(z), "f"(0.f) : "memory");
}

__device__ __forceinline__ float sigm_tanh(float v) {
    float t;
    asm("tanh.approx.f32 %0, %1;" : "=f"(t) : "f"(0.5f * v));
    return fmaf(0.5f, t, 0.5f);
}

// ---------------- degree histogram ----------------
__global__ void k_hist(const int4* __restrict__ src4) {
    int i = blockIdx.x * blockDim.x + threadIdx.x;
    if (i < EE / 4) {
        int4 v = src4[i];
        atomicAdd(&g_deg[v.x], 1);
        atomicAdd(&g_deg[v.y], 1);
        atomicAdd(&g_deg[v.z], 1);
        atomicAdd(&g_deg[v.w], 1);
    }
}

// ---------------- fold weights: M = W0 @ W1 @ [rowsum(wr0), wr1, wal] ----------------
__global__ void k_weights(const float* __restrict__ w0g, const float* __restrict__ w1g,
                          const float* __restrict__ wr0, const float* __restrict__ wr1,
                          const float* __restrict__ wal) {
    __shared__ float V[128][4];
    __shared__ float U[128][4];
    int k = threadIdx.x;  // 128 threads
    const float4* r0v = (const float4*)(wr0 + k * 128);
    float s = 0.f;
#pragma unroll 8
    for (int f = 0; f < 32; f++) {
        float4 v = r0v[f];
        s += v.x + v.y + v.z + v.w;
    }
    V[k][0] = s;
    V[k][1] = wr1[k];
    V[k][2] = wal[k];
    __syncthreads();
    float s0 = 0.f, s1 = 0.f, s2 = 0.f;
    for (int f = 0; f < 128; f++) {
        float w = w1g[k * 128 + f];
        s0 += w * V[f][0]; s1 += w * V[f][1]; s2 += w * V[f][2];
    }
    U[k][0] = s0; U[k][1] = s1; U[k][2] = s2;
    __syncthreads();
    s0 = s1 = s2 = 0.f;
    for (int f = 0; f < 128; f++) {
        float w = w0g[k * 128 + f];
        s0 += w * U[f][0]; s1 += w * U[f][1]; s2 += w * U[f][2];
    }
    g_M[k] = make_float4(s0, s1, s2, 0.f);
}

// ---------------- t_raw = h @ M  (warp per node, grid-stride, M in regs) ----------------
__global__ void __launch_bounds__(256) k_t(const float4* __restrict__ h4) {
    int lane = threadIdx.x & 31;
    int warp = (blockIdx.x * blockDim.x + threadIdx.x) >> 5;
    int nwarps = (gridDim.x * blockDim.x) >> 5;

    float4 m0 = g_M[lane * 4 + 0];
    float4 m1 = g_M[lane * 4 + 1];
    float4 m2 = g_M[lane * 4 + 2];
    float4 m3 = g_M[lane * 4 + 3];

    for (int node = warp; node < NN; node += nwarps) {
        float4 hv = __ldg(&h4[(size_t)node * 32 + lane]);

        float s0 = hv.x * m0.x + hv.y * m1.x + hv.z * m2.x + hv.w * m3.x;
        float s1 = hv.x * m0.y + hv.y * m1.y + hv.z * m2.y + hv.w * m3.y;
        float s2 = hv.x * m0.z + hv.y * m1.z + hv.z * m2.z + hv.w * m3.z;

#pragma unroll
        for (int o = 16; o; o >>= 1) {
            s0 += __shfl_xor_sync(0xffffffffu, s0, o);
            s1 += __shfl_xor_sync(0xffffffffu, s1, o);
            s2 += __shfl_xor_sync(0xffffffffu, s2, o);
        }
        if (lane == 0) g_t[node] = make_float4(s0, s1, s2, 0.f);
    }
}

// ---------------- join: norm = rsqrt(deg); t *= norm ----------------
__global__ void k_normscale() {
    int i = blockIdx.x * blockDim.x + threadIdx.x;
    if (i >= NN) return;
    float nm = rsqrtf((float)g_deg[i]);
    g_norm[i] = nm;
    float4 v = g_t[i];
    g_t[i] = make_float4(v.x * nm, v.y * nm, v.z * nm, 0.f);
}

// ---------------- pass 1: x[src] += t[dst]  (scatter RED, 2 edges/thread) ----------------
__global__ void k_agg1(const int2* __restrict__ src2, const int2* __restrict__ dst2) {
    int i = blockIdx.x * blockDim.x + threadIdx.x;
    if (i >= EE / 2) return;
    int2 s = src2[i];
    int2 d = dst2[i];
    float4 va = __ldg(&g_t[d.x]);
    float4 vb = __ldg(&g_t[d.y]);
    red_add_v4(&g_x[s.x], va.x, va.y, va.z);
    red_add_v4(&g_x[s.y], vb.x, vb.y, vb.z);
}

// ---------------- x *= norm^2 (between layers) ----------------
__global__ void k_scale2() {
    int i = blockIdx.x * blockDim.x + threadIdx.x;
    if (i >= NN) return;
    float nm = g_norm[i];
    float n2 = nm * nm;
    float4 v = g_x[i];
    g_x[i] = make_float4(v.x * n2, v.y * n2, v.z * n2, 0.f);
}

// ---------------- pass 2: s[src] += x[dst] ----------------
__global__ void k_agg2(const int2* __restrict__ src2, const int2* __restrict__ dst2) {
    int i = blockIdx.x * blockDim.x + threadIdx.x;
    if (i >= EE / 2) return;
    int2 s = src2[i];
    int2 d = dst2[i];
    float4 va = __ldg(&g_x[d.x]);
    float4 vb = __ldg(&g_x[d.y]);
    red_add_v4(&g_s[s.x], va.x, va.y, va.z);
    red_add_v4(&g_s[s.y], vb.x, vb.y, vb.z);
}

// ---------------- per-node finish: final norm + exp precompute ----------------
__global__ void k_finish() {
    int i = blockIdx.x * blockDim.x + threadIdx.x;
    if (i >= NN) return;
    float4 a = g_s[i];
    float nm = g_norm[i];
    float fx = a.x * nm, fy = a.y * nm, fz = a.z * nm;
    float4 p;
    p.x = expf(fx);          // e^{r0sum}
    p.y = expf(fy);          // e^{r1}
    p.z = fz;                // alpha scalar (raw)
    p.w = expf(128.f * fy);  // e^{128*r1}
    g_p[i] = p;
}

// ---------------- per-edge outputs [6, E] ----------------
__global__ void k_edge(const int* __restrict__ src, const int* __restrict__ dst,
                       const int* __restrict__ sfk, const int* __restrict__ dfk,
                       float* __restrict__ out) {
    int e = blockIdx.x * blockDim.x + threadIdx.x;
    if (e >= EE) return;
    int s = src[e];
    int d = dst[e];
    int a = min(sfk[e], NN - 1);  // JAX gather clamps OOB indices
    int b = min(dfk[e], NN - 1);

    float4 S = __ldg(&g_p[s]);
    float4 D = __ldg(&g_p[d]);
    float4 A = __ldg(&g_p[a]);
    float4 B = __ldg(&g_p[b]);

    out[e]          = S.x * D.x;            // exp(S.x + D.x)
    out[EE + e]     = S.y * D.y;            // exp(S.y + D.y)
    out[2 * EE + e] = sigm_tanh(S.z * D.z);
    out[3 * EE + e] = A.x * B.w;            // exp(A.x + 128*B.y)
    out[4 * EE + e] = A.y * B.y;            // exp(A.y + B.y)
    out[5 * EE + e] = sigm_tanh(S.z * B.z);
}

// ---------------- launch ----------------
extern "C" void kernel_launch(void* const* d_in, const int* in_sizes, int n_in,
                              void* d_out, int out_size) {
    const float* h   = (const float*)d_in[0];
    const float* w0g = (const float*)d_in[1];
    const float* w1g = (const float*)d_in[2];
    const float* wr0 = (const float*)d_in[3];
    const float* wr1 = (const float*)d_in[4];
    const float* wal = (const float*)d_in[5];
    const int* esrc  = (const int*)d_in[6];
    const int* edst  = (const int*)d_in[7];
    const int* sfk   = (const int*)d_in[8];
    const int* dfk   = (const int*)d_in[9];
    float* out = (float*)d_out;

    // one-time host-side resources (created on the uncaptured correctness call)
    static cudaStream_t s2 = nullptr;
    static cudaEvent_t ev0 = nullptr, ev2 = nullptr;
    if (!s2) {
        cudaStreamCreateWithFlags(&s2, cudaStreamNonBlocking);
        cudaEventCreateWithFlags(&ev0, cudaEventDisableTiming);
        cudaEventCreateWithFlags(&ev2, cudaEventDisableTiming);
    }

    void *degp = nullptr, *xp = nullptr, *sp = nullptr;
    cudaGetSymbolAddress(&degp, g_deg);
    cudaGetSymbolAddress(&xp, g_x);
    cudaGetSymbolAddress(&sp, g_s);

    // fork: s2 branch runs weights + t_raw + accumulator zeroing
    cudaEventRecord(ev0, 0);
    cudaStreamWaitEvent(s2, ev0, 0);

    // main stream: degree histogram
    cudaMemsetAsync(degp, 0, NN * sizeof(int), 0);
    k_hist<<<(EE / 4 + 255) / 256, 256>>>((const int4*)esrc);

    // s2: zero accumulators, fold weights, raw projection
    cudaMemsetAsync(xp, 0, NN * sizeof(float4), s2);
    cudaMemsetAsync(sp, 0, NN * sizeof(float4), s2);
    k_weights<<<1, 128, 0, s2>>>(w0g, w1g, wr0, wr1, wal);
    k_t<<<1536, 256, 0, s2>>>((const float4*)h);

    // join
    cudaEventRecord(ev2, s2);
    cudaStreamWaitEvent(0, ev2, 0);

    // norm + scale t
    k_normscale<<<(NN + 255) / 256, 256>>>();

    // two scatter-RED aggregation passes with inter-layer scaling
    k_agg1<<<(EE / 2 + 255) / 256, 256>>>((const int2*)esrc, (const int2*)edst);
    k_scale2<<<(NN + 255) / 256, 256>>>();
    k_agg2<<<(EE / 2 + 255) / 256, 256>>>((const int2*)esrc, (const int2*)edst);

    // per-node exp precompute
    k_finish<<<(NN + 255) / 256, 256>>>();

    // per-edge outputs
    k_edge<<<(EE + 255) / 256, 256>>>(esrc, edst, sfk, dfk, out);
}

// round 5
// speedup vs baseline: 6.5783x; 1.0934x over previous
#include <cuda_runtime.h>

#define NN 100000
#define EE 1600000

// ---------------- device scratch (allocation-free) ----------------
__device__ int   g_deg[NN];
__device__ float g_norm[NN];
__device__ __align__(16) float4 g_M[128];   // folded weights: 128 x (3 used + pad)
__device__ __align__(16) float4 g_t[NN];    // norm * (h @ M)
__device__ __align__(16) float4 g_x[NN];    // agg-1 accumulator; .w carries norm^2
__device__ __align__(16) float4 g_s[NN];    // agg-2 accumulator
__device__ __align__(16) float4 g_p[NN];    // precomputed per-node factors

// ---------------- helpers ----------------
__device__ __forceinline__ void red_add_v4(float4* addr, float x, float y, float z) {
    asm volatile("red.global.add.v4.f32 [%0], {%1, %2, %3, %4};"
                 :: "l"(addr), "f"(x), "f"(y), "f"(z), "f"(0.f) : "memory");
}

__device__ __forceinline__ float sigm_tanh(float v) {
    float t;
    asm("tanh.approx.f32 %0, %1;" : "=f"(t) : "f"(0.5f * v));
    return fmaf(0.5f, t, 0.5f);
}

// ---------------- degree histogram ----------------
__global__ void k_hist(const int4* __restrict__ src4) {
    int i = blockIdx.x * blockDim.x + threadIdx.x;
    if (i < EE / 4) {
        int4 v = src4[i];
        atomicAdd(&g_deg[v.x], 1);
        atomicAdd(&g_deg[v.y], 1);
        atomicAdd(&g_deg[v.z], 1);
        atomicAdd(&g_deg[v.w], 1);
    }
}

// ---------------- prep: norm + accumulator init (replaces 2 memsets + normscale) ----
__global__ void k_prep() {
    int i = blockIdx.x * blockDim.x + threadIdx.x;
    if (i >= NN) return;
    float nm = rsqrtf((float)g_deg[i]);
    g_norm[i] = nm;
    g_x[i] = make_float4(0.f, 0.f, 0.f, nm * nm);  // .w = inter-layer scale, RED-invariant
    g_s[i] = make_float4(0.f, 0.f, 0.f, 0.f);
}

// ---------------- fold weights: M = W0 @ W1 @ [rowsum(wr0), wr1, wal] ----------------
__global__ void k_weights(const float* __restrict__ w0g, const float* __restrict__ w1g,
                          const float* __restrict__ wr0, const float* __restrict__ wr1,
                          const float* __restrict__ wal) {
    __shared__ float V[128][4];
    __shared__ float U[128][4];
    int k = threadIdx.x;  // 128 threads
    const float4* r0v = (const float4*)(wr0 + k * 128);
    float s = 0.f;
#pragma unroll 8
    for (int f = 0; f < 32; f++) {
        float4 v = r0v[f];
        s += v.x + v.y + v.z + v.w;
    }
    V[k][0] = s;
    V[k][1] = wr1[k];
    V[k][2] = wal[k];
    __syncthreads();
    float s0 = 0.f, s1 = 0.f, s2 = 0.f;
    for (int f = 0; f < 128; f++) {
        float w = w1g[k * 128 + f];
        s0 += w * V[f][0]; s1 += w * V[f][1]; s2 += w * V[f][2];
    }
    U[k][0] = s0; U[k][1] = s1; U[k][2] = s2;
    __syncthreads();
    s0 = s1 = s2 = 0.f;
    for (int f = 0; f < 128; f++) {
        float w = w0g[k * 128 + f];
        s0 += w * U[f][0]; s1 += w * U[f][1]; s2 += w * U[f][2];
    }
    g_M[k] = make_float4(s0, s1, s2, 0.f);
}

// ---------------- t = norm * (h @ M)  (warp per node, grid-stride, M in regs) ------
__global__ void __launch_bounds__(256) k_t(const float4* __restrict__ h4) {
    int lane = threadIdx.x & 31;
    int warp = (blockIdx.x * blockDim.x + threadIdx.x) >> 5;
    int nwarps = (gridDim.x * blockDim.x) >> 5;

    float4 m0 = g_M[lane * 4 + 0];
    float4 m1 = g_M[lane * 4 + 1];
    float4 m2 = g_M[lane * 4 + 2];
    float4 m3 = g_M[lane * 4 + 3];

    for (int node = warp; node < NN; node += nwarps) {
        float4 hv = __ldg(&h4[(size_t)node * 32 + lane]);

        float s0 = hv.x * m0.x + hv.y * m1.x + hv.z * m2.x + hv.w * m3.x;
        float s1 = hv.x * m0.y + hv.y * m1.y + hv.z * m2.y + hv.w * m3.y;
        float s2 = hv.x * m0.z + hv.y * m1.z + hv.z * m2.z + hv.w * m3.z;

#pragma unroll
        for (int o = 16; o; o >>= 1) {
            s0 += __shfl_xor_sync(0xffffffffu, s0, o);
            s1 += __shfl_xor_sync(0xffffffffu, s1, o);
            s2 += __shfl_xor_sync(0xffffffffu, s2, o);
        }
        if (lane == 0) {
            float nm = g_norm[node];
            g_t[node] = make_float4(s0 * nm, s1 * nm, s2 * nm, 0.f);
        }
    }
}

// ---------------- pass 1: x[src] += t[dst]  (scatter RED, 2 edges/thread) ---------
__global__ void k_agg1(const int2* __restrict__ src2, const int2* __restrict__ dst2) {
    int i = blockIdx.x * blockDim.x + threadIdx.x;
    if (i >= EE / 2) return;
    int2 s = src2[i];
    int2 d = dst2[i];
    float4 va = __ldg(&g_t[d.x]);
    float4 vb = __ldg(&g_t[d.y]);
    red_add_v4(&g_x[s.x], va.x, va.y, va.z);
    red_add_v4(&g_x[s.y], vb.x, vb.y, vb.z);
}

// ---------------- pass 2: s[src] += x[dst].xyz * x[dst].w  (fused scale) ----------
__global__ void k_agg2(const int2* __restrict__ src2, const int2* __restrict__ dst2) {
    int i = blockIdx.x * blockDim.x + threadIdx.x;
    if (i >= EE / 2) return;
    int2 s = src2[i];
    int2 d = dst2[i];
    float4 va = __ldg(&g_x[d.x]);
    float4 vb = __ldg(&g_x[d.y]);
    red_add_v4(&g_s[s.x], va.x * va.w, va.y * va.w, va.z * va.w);
    red_add_v4(&g_s[s.y], vb.x * vb.w, vb.y * vb.w, vb.z * vb.w);
}

// ---------------- per-node finish: final norm + exp precompute --------------------
__global__ void k_finish() {
    int i = blockIdx.x * blockDim.x + threadIdx.x;
    if (i >= NN) return;
    float4 a = g_s[i];
    float nm = g_norm[i];
    float fx = a.x * nm, fy = a.y * nm, fz = a.z * nm;
    float4 p;
    p.x = expf(fx);          // e^{r0sum}
    p.y = expf(fy);          // e^{r1}
    p.z = fz;                // alpha scalar (raw)
    p.w = expf(128.f * fy);  // e^{128*r1}
    g_p[i] = p;
}

// ---------------- per-edge outputs [6, E]  (2 edges/thread) -----------------------
__global__ void __launch_bounds__(256) k_edge(const int2* __restrict__ src,
                                              const int2* __restrict__ dst,
                                              const int2* __restrict__ sfk,
                                              const int2* __restrict__ dfk,
                                              float* __restrict__ out) {
    int i = blockIdx.x * blockDim.x + threadIdx.x;
    if (i >= EE / 2) return;
    int2 s2v = src[i];
    int2 d2v = dst[i];
    int2 a2v = sfk[i];
    int2 b2v = dfk[i];
    int a0 = min(a2v.x, NN - 1), a1 = min(a2v.y, NN - 1);  // JAX clamp
    int b0 = min(b2v.x, NN - 1), b1 = min(b2v.y, NN - 1);

    float4 S0 = __ldg(&g_p[s2v.x]);
    float4 S1 = __ldg(&g_p[s2v.y]);
    float4 D0 = __ldg(&g_p[d2v.x]);
    float4 D1 = __ldg(&g_p[d2v.y]);
    float4 A0 = __ldg(&g_p[a0]);
    float4 A1 = __ldg(&g_p[a1]);
    float4 B0 = __ldg(&g_p[b0]);
    float4 B1 = __ldg(&g_p[b1]);

    int e = i * 2;
    float2* o0 = (float2*)(out + e);
    float2* o1 = (float2*)(out + EE + e);
    float2* o2 = (float2*)(out + 2 * EE + e);
    float2* o3 = (float2*)(out + 3 * EE + e);
    float2* o4 = (float2*)(out + 4 * EE + e);
    float2* o5 = (float2*)(out + 5 * EE + e);

    *o0 = make_float2(S0.x * D0.x, S1.x * D1.x);
    *o1 = make_float2(S0.y * D0.y, S1.y * D1.y);
    *o2 = make_float2(sigm_tanh(S0.z * D0.z), sigm_tanh(S1.z * D1.z));
    *o3 = make_float2(A0.x * B0.w, A1.x * B1.w);
    *o4 = make_float2(A0.y * B0.y, A1.y * B1.y);
    *o5 = make_float2(sigm_tanh(S0.z * B0.z), sigm_tanh(S1.z * B1.z));
}

// ---------------- launch ----------------
extern "C" void kernel_launch(void* const* d_in, const int* in_sizes, int n_in,
                              void* d_out, int out_size) {
    const float* h   = (const float*)d_in[0];
    const float* w0g = (const float*)d_in[1];
    const float* w1g = (const float*)d_in[2];
    const float* wr0 = (const float*)d_in[3];
    const float* wr1 = (const float*)d_in[4];
    const float* wal = (const float*)d_in[5];
    const int* esrc  = (const int*)d_in[6];
    const int* edst  = (const int*)d_in[7];
    const int* sfk   = (const int*)d_in[8];
    const int* dfk   = (const int*)d_in[9];
    float* out = (float*)d_out;

    // one-time host-side resources (created on the uncaptured correctness call)
    static cudaStream_t s2 = nullptr;
    static cudaEvent_t ev0 = nullptr, ev2 = nullptr;
    if (!s2) {
        cudaStreamCreateWithFlags(&s2, cudaStreamNonBlocking);
        cudaEventCreateWithFlags(&ev0, cudaEventDisableTiming);
        cudaEventCreateWithFlags(&ev2, cudaEventDisableTiming);
    }

    void* degp = nullptr;
    cudaGetSymbolAddress(&degp, g_deg);

    // fork: s2 folds weights concurrently with degree histogram
    cudaEventRecord(ev0, 0);
    cudaStreamWaitEvent(s2, ev0, 0);
    k_weights<<<1, 128, 0, s2>>>(w0g, w1g, wr0, wr1, wal);
    cudaEventRecord(ev2, s2);

    // main: degree histogram -> prep (norm + accumulator init)
    cudaMemsetAsync(degp, 0, NN * sizeof(int), 0);
    k_hist<<<(EE / 4 + 255) / 256, 256>>>((const int4*)esrc);
    k_prep<<<(NN + 255) / 256, 256>>>();

    // join (weights) then projection t = norm * (h @ M)
    cudaStreamWaitEvent(0, ev2, 0);
    k_t<<<1536, 256>>>((const float4*)h);

    // two scatter-RED aggregation passes (scale fused via g_x.w)
    k_agg1<<<(EE / 2 + 255) / 256, 256>>>((const int2*)esrc, (const int2*)edst);
    k_agg2<<<(EE / 2 + 255) / 256, 256>>>((const int2*)esrc, (const int2*)edst);

    // per-node exp precompute
    k_finish<<<(NN + 255) / 256, 256>>>();

    // per-edge outputs
    k_edge<<<(EE / 2 + 255) / 256, 256>>>((const int2*)esrc, (const int2*)edst,
                                          (const int2*)sfk, (const int2*)dfk, out);
}

// round 6
// speedup vs baseline: 6.9048x; 1.0496x over previous
#include <cuda_runtime.h>

#define NN 100000
#define EE 1600000

// ---------------- device scratch (allocation-free) ----------------
__device__ int   g_deg[NN];
__device__ float g_norm[NN];
__device__ __align__(16) float4 g_M[128];   // folded weights: 128 x (3 used + pad)
__device__ __align__(16) float4 g_t[NN];    // norm * (h @ M)
__device__ __align__(16) float4 g_x[NN];    // agg-1 accumulator; .w carries norm^2
__device__ __align__(16) float4 g_s[NN];    // agg-2 accumulator
__device__ __align__(16) float4 g_p[NN];    // precomputed per-node factors

// ---------------- helpers ----------------
__device__ __forceinline__ void red_add_v4(float4* addr, float x, float y, float z) {
    asm volatile("red.global.add.v4.f32 [%0], {%1, %2, %3, %4};"
                 :: "l"(addr), "f"(x), "f"(y), "f"(z), "f"(0.f) : "memory");
}

__device__ __forceinline__ float sigm_tanh(float v) {
    float t;
    asm("tanh.approx.f32 %0, %1;" : "=f"(t) : "f"(0.5f * v));
    return fmaf(0.5f, t, 0.5f);
}

// ---------------- degree histogram (8 edges/thread) ----------------
__global__ void k_hist(const int4* __restrict__ src4) {
    int i = (blockIdx.x * blockDim.x + threadIdx.x) * 2;
    if (i < EE / 4) {
        int4 v = src4[i];
        atomicAdd(&g_deg[v.x], 1);
        atomicAdd(&g_deg[v.y], 1);
        atomicAdd(&g_deg[v.z], 1);
        atomicAdd(&g_deg[v.w], 1);
        int4 w = src4[i + 1];
        atomicAdd(&g_deg[w.x], 1);
        atomicAdd(&g_deg[w.y], 1);
        atomicAdd(&g_deg[w.z], 1);
        atomicAdd(&g_deg[w.w], 1);
    }
}

// ---------------- prep: norm + accumulator init ----------------
__global__ void k_prep() {
    int i = blockIdx.x * blockDim.x + threadIdx.x;
    if (i >= NN) return;
    float nm = rsqrtf((float)g_deg[i]);
    g_norm[i] = nm;
    g_x[i] = make_float4(0.f, 0.f, 0.f, nm * nm);  // .w = inter-layer scale, RED-invariant
    g_s[i] = make_float4(0.f, 0.f, 0.f, 0.f);
}

// ---------------- fold weights: M = W0 @ W1 @ [rowsum(wr0), wr1, wal] -------------
__global__ void k_weights(const float* __restrict__ w0g, const float* __restrict__ w1g,
                          const float* __restrict__ wr0, const float* __restrict__ wr1,
                          const float* __restrict__ wal) {
    __shared__ float V[128][4];
    __shared__ float U[128][4];
    int k = threadIdx.x;  // 128 threads
    const float4* r0v = (const float4*)(wr0 + k * 128);
    float s = 0.f;
#pragma unroll 8
    for (int f = 0; f < 32; f++) {
        float4 v = r0v[f];
        s += v.x + v.y + v.z + v.w;
    }
    V[k][0] = s;
    V[k][1] = wr1[k];
    V[k][2] = wal[k];
    __syncthreads();
    float s0 = 0.f, s1 = 0.f, s2 = 0.f;
    for (int f = 0; f < 128; f++) {
        float w = w1g[k * 128 + f];
        s0 += w * V[f][0]; s1 += w * V[f][1]; s2 += w * V[f][2];
    }
    U[k][0] = s0; U[k][1] = s1; U[k][2] = s2;
    __syncthreads();
    s0 = s1 = s2 = 0.f;
    for (int f = 0; f < 128; f++) {
        float w = w0g[k * 128 + f];
        s0 += w * U[f][0]; s1 += w * U[f][1]; s2 += w * U[f][2];
    }
    g_M[k] = make_float4(s0, s1, s2, 0.f);
}

// ---------------- t = norm * (h @ M)  (warp per 4 nodes, interleaved reductions) ---
__global__ void __launch_bounds__(256) k_t(const float4* __restrict__ h4) {
    int lane = threadIdx.x & 31;
    int warp = (blockIdx.x * blockDim.x + threadIdx.x) >> 5;
    int nwarps = (gridDim.x * blockDim.x) >> 5;

    float4 m0 = g_M[lane * 4 + 0];
    float4 m1 = g_M[lane * 4 + 1];
    float4 m2 = g_M[lane * 4 + 2];
    float4 m3 = g_M[lane * 4 + 3];

    for (int base = warp * 4; base < NN; base += nwarps * 4) {
        float a[4][3];
#pragma unroll
        for (int j = 0; j < 4; j++) {
            int node = base + j;
            float4 hv = make_float4(0.f, 0.f, 0.f, 0.f);
            if (node < NN) hv = __ldg(&h4[(size_t)node * 32 + lane]);
            a[j][0] = hv.x * m0.x + hv.y * m1.x + hv.z * m2.x + hv.w * m3.x;
            a[j][1] = hv.x * m0.y + hv.y * m1.y + hv.z * m2.y + hv.w * m3.y;
            a[j][2] = hv.x * m0.z + hv.y * m1.z + hv.z * m2.z + hv.w * m3.z;
        }
        // 12 interleaved butterfly chains (independent -> pipelined)
#pragma unroll
        for (int o = 16; o; o >>= 1) {
#pragma unroll
            for (int j = 0; j < 4; j++) {
                a[j][0] += __shfl_xor_sync(0xffffffffu, a[j][0], o);
                a[j][1] += __shfl_xor_sync(0xffffffffu, a[j][1], o);
                a[j][2] += __shfl_xor_sync(0xffffffffu, a[j][2], o);
            }
        }
        if (lane == 0) {
#pragma unroll
            for (int j = 0; j < 4; j++) {
                int node = base + j;
                if (node < NN) {
                    float nm = g_norm[node];
                    g_t[node] = make_float4(a[j][0] * nm, a[j][1] * nm, a[j][2] * nm, 0.f);
                }
            }
        }
    }
}

// ---------------- pass 1: x[src] += t[dst]  (scatter RED, 4 edges/thread) ---------
__global__ void k_agg1(const int4* __restrict__ src4, const int4* __restrict__ dst4) {
    int i = blockIdx.x * blockDim.x + threadIdx.x;
    if (i >= EE / 4) return;
    int4 s = src4[i];
    int4 d = dst4[i];
    float4 va = __ldg(&g_t[d.x]);
    float4 vb = __ldg(&g_t[d.y]);
    float4 vc = __ldg(&g_t[d.z]);
    float4 vd = __ldg(&g_t[d.w]);
    red_add_v4(&g_x[s.x], va.x, va.y, va.z);
    red_add_v4(&g_x[s.y], vb.x, vb.y, vb.z);
    red_add_v4(&g_x[s.z], vc.x, vc.y, vc.z);
    red_add_v4(&g_x[s.w], vd.x, vd.y, vd.z);
}

// ---------------- pass 2: s[src] += x[dst].xyz * x[dst].w  (fused scale) ----------
__global__ void k_agg2(const int4* __restrict__ src4, const int4* __restrict__ dst4) {
    int i = blockIdx.x * blockDim.x + threadIdx.x;
    if (i >= EE / 4) return;
    int4 s = src4[i];
    int4 d = dst4[i];
    float4 va = __ldg(&g_x[d.x]);
    float4 vb = __ldg(&g_x[d.y]);
    float4 vc = __ldg(&g_x[d.z]);
    float4 vd = __ldg(&g_x[d.w]);
    red_add_v4(&g_s[s.x], va.x * va.w, va.y * va.w, va.z * va.w);
    red_add_v4(&g_s[s.y], vb.x * vb.w, vb.y * vb.w, vb.z * vb.w);
    red_add_v4(&g_s[s.z], vc.x * vc.w, vc.y * vc.w, vc.z * vc.w);
    red_add_v4(&g_s[s.w], vd.x * vd.w, vd.y * vd.w, vd.z * vd.w);
}

// ---------------- per-node finish: final norm + exp precompute --------------------
__global__ void k_finish() {
    int i = blockIdx.x * blockDim.x + threadIdx.x;
    if (i >= NN) return;
    float4 a = g_s[i];
    float nm = g_norm[i];
    float fx = a.x * nm, fy = a.y * nm, fz = a.z * nm;
    float4 p;
    p.x = expf(fx);          // e^{r0sum}
    p.y = expf(fy);          // e^{r1}
    p.z = fz;                // alpha scalar (raw)
    p.w = expf(128.f * fy);  // e^{128*r1}
    g_p[i] = p;
}

// ---------------- per-edge outputs [6, E]  (2 edges/thread) -----------------------
__global__ void __launch_bounds__(256) k_edge(const int2* __restrict__ src,
                                              const int2* __restrict__ dst,
                                              const int2* __restrict__ sfk,
                                              const int2* __restrict__ dfk,
                                              float* __restrict__ out) {
    int i = blockIdx.x * blockDim.x + threadIdx.x;
    if (i >= EE / 2) return;
    int2 s2v = src[i];
    int2 d2v = dst[i];
    int2 a2v = sfk[i];
    int2 b2v = dfk[i];
    int a0 = min(a2v.x, NN - 1), a1 = min(a2v.y, NN - 1);  // JAX clamp
    int b0 = min(b2v.x, NN - 1), b1 = min(b2v.y, NN - 1);

    float4 S0 = __ldg(&g_p[s2v.x]);
    float4 S1 = __ldg(&g_p[s2v.y]);
    float4 D0 = __ldg(&g_p[d2v.x]);
    float4 D1 = __ldg(&g_p[d2v.y]);
    float4 A0 = __ldg(&g_p[a0]);
    float4 A1 = __ldg(&g_p[a1]);
    float4 B0 = __ldg(&g_p[b0]);
    float4 B1 = __ldg(&g_p[b1]);

    int e = i * 2;
    float2* o0 = (float2*)(out + e);
    float2* o1 = (float2*)(out + EE + e);
    float2* o2 = (float2*)(out + 2 * EE + e);
    float2* o3 = (float2*)(out + 3 * EE + e);
    float2* o4 = (float2*)(out + 4 * EE + e);
    float2* o5 = (float2*)(out + 5 * EE + e);

    *o0 = make_float2(S0.x * D0.x, S1.x * D1.x);
    *o1 = make_float2(S0.y * D0.y, S1.y * D1.y);
    *o2 = make_float2(sigm_tanh(S0.z * D0.z), sigm_tanh(S1.z * D1.z));
    *o3 = make_float2(A0.x * B0.w, A1.x * B1.w);
    *o4 = make_float2(A0.y * B0.y, A1.y * B1.y);
    *o5 = make_float2(sigm_tanh(S0.z * B0.z), sigm_tanh(S1.z * B1.z));
}

// ---------------- launch ----------------
extern "C" void kernel_launch(void* const* d_in, const int* in_sizes, int n_in,
                              void* d_out, int out_size) {
    const float* h   = (const float*)d_in[0];
    const float* w0g = (const float*)d_in[1];
    const float* w1g = (const float*)d_in[2];
    const float* wr0 = (const float*)d_in[3];
    const float* wr1 = (const float*)d_in[4];
    const float* wal = (const float*)d_in[5];
    const int* esrc  = (const int*)d_in[6];
    const int* edst  = (const int*)d_in[7];
    const int* sfk   = (const int*)d_in[8];
    const int* dfk   = (const int*)d_in[9];
    float* out = (float*)d_out;

    // one-time host-side resources (created on the uncaptured correctness call)
    static cudaStream_t s2 = nullptr;
    static cudaEvent_t ev0 = nullptr, ev2 = nullptr;
    if (!s2) {
        cudaStreamCreateWithFlags(&s2, cudaStreamNonBlocking);
        cudaEventCreateWithFlags(&ev0, cudaEventDisableTiming);
        cudaEventCreateWithFlags(&ev2, cudaEventDisableTiming);
    }

    void* degp = nullptr;
    cudaGetSymbolAddress(&degp, g_deg);

    // fork: s2 folds weights concurrently with degree histogram
    cudaEventRecord(ev0, 0);
    cudaStreamWaitEvent(s2, ev0, 0);
    k_weights<<<1, 128, 0, s2>>>(w0g, w1g, wr0, wr1, wal);
    cudaEventRecord(ev2, s2);

    // main: degree histogram -> prep (norm + accumulator init)
    cudaMemsetAsync(degp, 0, NN * sizeof(int), 0);
    k_hist<<<(EE / 8 + 255) / 256, 256>>>((const int4*)esrc);
    k_prep<<<(NN + 255) / 256, 256>>>();

    // join (weights) then projection t = norm * (h @ M)
    cudaStreamWaitEvent(0, ev2, 0);
    k_t<<<1536, 256>>>((const float4*)h);

    // two scatter-RED aggregation passes (scale fused via g_x.w)
    k_agg1<<<(EE / 4 + 255) / 256, 256>>>((const int4*)esrc, (const int4*)edst);
    k_agg2<<<(EE / 4 + 255) / 256, 256>>>((const int4*)esrc, (const int4*)edst);

    // per-node exp precompute
    k_finish<<<(NN + 255) / 256, 256>>>();

    // per-edge outputs
    k_edge<<<(EE / 2 + 255) / 256, 256>>>((const int2*)esrc, (const int2*)edst,
                                          (const int2*)sfk, (const int2*)dfk, out);
}